// round 7
// baseline (speedup 1.0000x reference)
#include <cuda_runtime.h>
#include <cuda_bf16.h>

// ============================================================================
// prep_kernel: per-node constants -> g_node4 (4 float4 per node):
//   [0] r00 r01 r02 u0
//   [1] r10 r11 r12 u1
//   [2] r20 r21 r22 u2
//   [3] kx  ky  kz  kc
// u  = t + c - R*c          (contribution = w * (R*p + u))
// k  = 2*SS2*c, kc = -SS2*|c|^2,  SS2 = log2(e)/(2*sigma^2)
// w  = ex2( k.p + kc - SS2*|p|^2 )
//
// main_kernel: block 0 = edge regularizer; blocks 1.. = points (1 pt/thread,
// 64-thread blocks). Node constants read via uniform LDG (L1-resident 32KB).
// ============================================================================

#define MAXN 4096
__device__ float4 g_node4[MAXN * 4];

#define SS2 0.0288539008f   // 0.02 * log2(e)

__device__ __forceinline__ float ex2f(float x) {
    float r;
    asm("ex2.approx.f32 %0, %1;" : "=f"(r) : "f"(x));
    return r;
}

// ---- Rodrigues --------------------------------------------------------------
__device__ __forceinline__ void rodrigues(float x, float y, float z, float R[9]) {
    float th2 = x * x + y * y + z * z + 1e-12f;
    float th = sqrtf(th2);
    float s, co;
    sincosf(th, &s, &co);
    float a = s / th;
    float b = (1.0f - co) / th2;
    float xx = x * x, yy = y * y, zz = z * z;
    float xy = x * y, xz = x * z, yz = y * z;
    R[0] = 1.0f - b * (yy + zz);
    R[1] = -a * z + b * xy;
    R[2] =  a * y + b * xz;
    R[3] =  a * z + b * xy;
    R[4] = 1.0f - b * (xx + zz);
    R[5] = -a * x + b * yz;
    R[6] = -a * y + b * xz;
    R[7] =  a * x + b * yz;
    R[8] = 1.0f - b * (xx + yy);
}

// ---------------------------------------------------------------------------
__global__ void __launch_bounds__(64)
prep_kernel(const float* __restrict__ cp,
            const float* __restrict__ rv,
            const float* __restrict__ t,
            int N) {
    int n = blockIdx.x * 64 + threadIdx.x;
    if (n >= N) return;

    float R[9];
    rodrigues(rv[3 * n + 0], rv[3 * n + 1], rv[3 * n + 2], R);
    float cx = cp[3 * n + 0], cy = cp[3 * n + 1], cz = cp[3 * n + 2];
    float tx = t[3 * n + 0],  ty = t[3 * n + 1],  tz = t[3 * n + 2];
    float u0 = tx + cx - (R[0] * cx + R[1] * cy + R[2] * cz);
    float u1 = ty + cy - (R[3] * cx + R[4] * cy + R[5] * cz);
    float u2 = tz + cz - (R[6] * cx + R[7] * cy + R[8] * cz);

    g_node4[4 * n + 0] = make_float4(R[0], R[1], R[2], u0);
    g_node4[4 * n + 1] = make_float4(R[3], R[4], R[5], u1);
    g_node4[4 * n + 2] = make_float4(R[6], R[7], R[8], u2);
    g_node4[4 * n + 3] = make_float4(2.0f * SS2 * cx, 2.0f * SS2 * cy,
                                     2.0f * SS2 * cz,
                                     -SS2 * (cx * cx + cy * cy + cz * cz));
}

// ---------------------------------------------------------------------------
__global__ void __launch_bounds__(64)
main_kernel(const float* __restrict__ pts,
            const float* __restrict__ cp,
            const float* __restrict__ t,
            const int* __restrict__ edges,
            float* __restrict__ out,
            int N, int P, int E) {
    // ------------------------------------------------------------------
    // Block 0: edge regularizer.
    // resid = (R_i * c_j + u_i) - (c_j + t_j)
    // ------------------------------------------------------------------
    if (blockIdx.x == 0) {
        __shared__ float red[64];
        float acc = 0.0f;
        for (int m = threadIdx.x; m < E; m += 64) {
            int i = edges[2 * m + 0];
            int j = edges[2 * m + 1];
            i = min(max(i, 0), N - 1);
            j = min(max(j, 0), N - 1);

            float4 a = g_node4[4 * i + 0];
            float4 b = g_node4[4 * i + 1];
            float4 c = g_node4[4 * i + 2];

            float cjx = cp[3 * j + 0], cjy = cp[3 * j + 1], cjz = cp[3 * j + 2];
            float tjx = t[3 * j + 0],  tjy = t[3 * j + 1],  tjz = t[3 * j + 2];

            float r0 = fmaf(a.x, cjx, fmaf(a.y, cjy, fmaf(a.z, cjz, a.w))) - cjx - tjx;
            float r1 = fmaf(b.x, cjx, fmaf(b.y, cjy, fmaf(b.z, cjz, b.w))) - cjy - tjy;
            float r2 = fmaf(c.x, cjx, fmaf(c.y, cjy, fmaf(c.z, cjz, c.w))) - cjz - tjz;

            acc += r0 * r0 + r1 * r1 + r2 * r2;
        }
        red[threadIdx.x] = acc;
        __syncthreads();
        for (int s = 32; s > 0; s >>= 1) {
            if (threadIdx.x < (unsigned)s) red[threadIdx.x] += red[threadIdx.x + s];
            __syncthreads();
        }
        if (threadIdx.x == 0) out[3 * P] = red[0];
        return;
    }

    // ------------------------------------------------------------------
    // Point blocks: 1 point per thread.
    // ------------------------------------------------------------------
    int p = (blockIdx.x - 1) * 64 + threadIdx.x;
    if (p >= P) return;

    float px = pts[3 * p + 0];
    float py = pts[3 * p + 1];
    float pz = pts[3 * p + 2];
    float q2 = SS2 * (px * px + py * py + pz * pz);

    float ax = 0.0f, ay = 0.0f, az = 0.0f, S = 0.0f;

    const float4* __restrict__ gn = g_node4;

#pragma unroll 4
    for (int n = 0; n < N; ++n) {
        float4 a = gn[4 * n + 0];
        float4 b = gn[4 * n + 1];
        float4 c = gn[4 * n + 2];
        float4 k = gn[4 * n + 3];

        float arg = fmaf(k.x, px, fmaf(k.y, py, fmaf(k.z, pz, k.w))) - q2;
        float w = ex2f(arg);

        float y0 = fmaf(a.x, px, fmaf(a.y, py, fmaf(a.z, pz, a.w)));
        float y1 = fmaf(b.x, px, fmaf(b.y, py, fmaf(b.z, pz, b.w)));
        float y2 = fmaf(c.x, px, fmaf(c.y, py, fmaf(c.z, pz, c.w)));

        ax = fmaf(w, y0, ax);
        ay = fmaf(w, y1, ay);
        az = fmaf(w, y2, az);
        S += w;
    }

    float inv = 1.0f / (S + 1e-5f);
    out[3 * p + 0] = ax * inv;
    out[3 * p + 1] = ay * inv;
    out[3 * p + 2] = az * inv;
}

// ---------------------------------------------------------------------------
extern "C" void kernel_launch(void* const* d_in, const int* in_sizes, int n_in,
                              void* d_out, int out_size) {
    const float* points  = (const float*)d_in[0];
    const float* cp      = (const float*)d_in[1];
    const float* rot_vec = (const float*)d_in[2];
    const float* t       = (const float*)d_in[3];
    const int*   edges   = (const int*)d_in[4];

    float* out = (float*)d_out;

    int P = in_sizes[0] / 3;
    int N = in_sizes[1] / 3;
    if (N > MAXN) N = MAXN;  // defensive
    int E = in_sizes[4] / 2;

    prep_kernel<<<(N + 63) / 64, 64>>>(cp, rot_vec, t, N);

    int nPointBlocks = (P + 63) / 64;
    main_kernel<<<nPointBlocks + 1, 64>>>(points, cp, t, edges, out, N, P, E);
}

// round 8
// speedup vs baseline: 3.0436x; 3.0436x over previous
#include <cuda_runtime.h>
#include <cuda_bf16.h>

// ============================================================================
// Single main kernel:
//   blocks [0, nTiles*NSPLIT): point work. tile = bid % nTiles, split = bid / nTiles.
//     Each block: 512 points (4/thread, 128 threads, 2 packed f32x2 pairs)
//     x 64 nodes (N/NSPLIT). Writes partials; LAST split-block of each tile
//     (atomic counter) combines all NSPLIT partials in FIXED order -> out.
//   block nTiles*NSPLIT: edge regularizer.
//
// smem per node: 16 replicated float2 slots (128 B):
//   0:r00 1:r01 2:r02 3:u0  4:r10 5:r11 6:r12 7:u1
//   8:r20 9:r21 10:r22 11:u2 12:kx 13:ky 14:kz 15:kc
// u  = t + c - R*c           (contribution = w * (R*p + u))
// k  = 2*SS2*c, kc = -SS2*|c|^2,  SS2 = log2(e)/(2*sigma^2)
// w  = ex2( k.p + kc - SS2*|p|^2 )
// ============================================================================

#define BLOCK_THREADS 128
#define PTS_PER_BLOCK 512      // 4 points per thread
#define NSPLIT 8
#define MAXP 65536
#define MAXTILES (MAXP / PTS_PER_BLOCK + 1)

__device__ float4 g_part[NSPLIT * MAXP];        // (ax, ay, az, S) partials
__device__ unsigned int g_tilecount[MAXTILES];  // monotone counters (mod NSPLIT)

// ---- packed f32x2 helpers (sm_103a) ----------------------------------------
__device__ __forceinline__ unsigned long long pk2(float a, float b) {
    unsigned long long r;
    asm("mov.b64 %0, {%1, %2};" : "=l"(r) : "f"(a), "f"(b));
    return r;
}
__device__ __forceinline__ void upk2(unsigned long long v, float& a, float& b) {
    asm("mov.b64 {%0, %1}, %2;" : "=f"(a), "=f"(b) : "l"(v));
}
__device__ __forceinline__ unsigned long long add2(unsigned long long a, unsigned long long b) {
    unsigned long long r;
    asm("add.rn.f32x2 %0, %1, %2;" : "=l"(r) : "l"(a), "l"(b));
    return r;
}
__device__ __forceinline__ unsigned long long fma2(unsigned long long a, unsigned long long b,
                                                   unsigned long long c) {
    unsigned long long r;
    asm("fma.rn.f32x2 %0, %1, %2, %3;" : "=l"(r) : "l"(a), "l"(b), "l"(c));
    return r;
}
__device__ __forceinline__ float ex2f(float x) {
    float r;
    asm("ex2.approx.f32 %0, %1;" : "=f"(r) : "f"(x));
    return r;
}

// ---- Rodrigues --------------------------------------------------------------
__device__ __forceinline__ void rodrigues(float x, float y, float z, float R[9]) {
    float th2 = x * x + y * y + z * z + 1e-12f;
    float th = sqrtf(th2);
    float s, co;
    sincosf(th, &s, &co);
    float a = s / th;
    float b = (1.0f - co) / th2;
    float xx = x * x, yy = y * y, zz = z * z;
    float xy = x * y, xz = x * z, yz = y * z;
    R[0] = 1.0f - b * (yy + zz);
    R[1] = -a * z + b * xy;
    R[2] =  a * y + b * xz;
    R[3] =  a * z + b * xy;
    R[4] = 1.0f - b * (xx + zz);
    R[5] = -a * x + b * yz;
    R[6] = -a * y + b * xz;
    R[7] =  a * x + b * yz;
    R[8] = 1.0f - b * (xx + yy);
}

// SS2 = (1/(2*sigma^2)) * log2(e) = 0.02 * 1.44269504
#define SS2 0.0288539008f

__global__ void __launch_bounds__(BLOCK_THREADS)
main_kernel(const float* __restrict__ pts,
            const float* __restrict__ cp,
            const float* __restrict__ rv,
            const float* __restrict__ t,
            const int* __restrict__ edges,
            float* __restrict__ out,
            int N, int P, int E, int nTiles, int chunk) {
    extern __shared__ float2 sf[];  // 16 replicated float2 per local node

    // ------------------------------------------------------------------
    // Edge block (last block)
    // ------------------------------------------------------------------
    if (blockIdx.x == (unsigned)(nTiles * NSPLIT)) {
        __shared__ float red[BLOCK_THREADS];
        float acc = 0.0f;
        for (int m = threadIdx.x; m < E; m += BLOCK_THREADS) {
            int i = edges[2 * m + 0];
            int j = edges[2 * m + 1];
            i = min(max(i, 0), N - 1);
            j = min(max(j, 0), N - 1);

            float R[9];
            rodrigues(rv[3 * i + 0], rv[3 * i + 1], rv[3 * i + 2], R);

            float cix = cp[3 * i + 0], ciy = cp[3 * i + 1], ciz = cp[3 * i + 2];
            float cjx = cp[3 * j + 0], cjy = cp[3 * j + 1], cjz = cp[3 * j + 2];
            float tix = t[3 * i + 0],  tiy = t[3 * i + 1],  tiz = t[3 * i + 2];
            float tjx = t[3 * j + 0],  tjy = t[3 * j + 1],  tjz = t[3 * j + 2];

            float dx = cjx - cix, dy = cjy - ciy, dz = cjz - ciz;

            float r0 = fmaf(R[0], dx, fmaf(R[1], dy, R[2] * dz)) + cix + tix - cjx - tjx;
            float r1 = fmaf(R[3], dx, fmaf(R[4], dy, R[5] * dz)) + ciy + tiy - cjy - tjy;
            float r2 = fmaf(R[6], dx, fmaf(R[7], dy, R[8] * dz)) + ciz + tiz - cjz - tjz;

            acc += r0 * r0 + r1 * r1 + r2 * r2;
        }
        red[threadIdx.x] = acc;
        __syncthreads();
        for (int s = BLOCK_THREADS / 2; s > 0; s >>= 1) {
            if (threadIdx.x < (unsigned)s) red[threadIdx.x] += red[threadIdx.x + s];
            __syncthreads();
        }
        if (threadIdx.x == 0) out[3 * P] = red[0];
        return;
    }

    int split = blockIdx.x / nTiles;
    int tile  = blockIdx.x % nTiles;
    int n0 = split * chunk;
    int nNodes = min(chunk, N - n0);
    if (nNodes < 0) nNodes = 0;

    // ------------------------------------------------------------------
    // Stage this split's node constants
    // ------------------------------------------------------------------
    for (int ln = threadIdx.x; ln < nNodes; ln += BLOCK_THREADS) {
        int n = n0 + ln;
        float R[9];
        rodrigues(rv[3 * n + 0], rv[3 * n + 1], rv[3 * n + 2], R);
        float cx = cp[3 * n + 0], cy = cp[3 * n + 1], cz = cp[3 * n + 2];
        float tx = t[3 * n + 0],  ty = t[3 * n + 1],  tz = t[3 * n + 2];
        float u0 = tx + cx - (R[0] * cx + R[1] * cy + R[2] * cz);
        float u1 = ty + cy - (R[3] * cx + R[4] * cy + R[5] * cz);
        float u2 = tz + cz - (R[6] * cx + R[7] * cy + R[8] * cz);
        float kx = 2.0f * SS2 * cx;
        float ky = 2.0f * SS2 * cy;
        float kz = 2.0f * SS2 * cz;
        float kc = -SS2 * (cx * cx + cy * cy + cz * cz);

        float2* s = sf + 16 * ln;
        s[0]  = make_float2(R[0], R[0]);
        s[1]  = make_float2(R[1], R[1]);
        s[2]  = make_float2(R[2], R[2]);
        s[3]  = make_float2(u0, u0);
        s[4]  = make_float2(R[3], R[3]);
        s[5]  = make_float2(R[4], R[4]);
        s[6]  = make_float2(R[5], R[5]);
        s[7]  = make_float2(u1, u1);
        s[8]  = make_float2(R[6], R[6]);
        s[9]  = make_float2(R[7], R[7]);
        s[10] = make_float2(R[8], R[8]);
        s[11] = make_float2(u2, u2);
        s[12] = make_float2(kx, kx);
        s[13] = make_float2(ky, ky);
        s[14] = make_float2(kz, kz);
        s[15] = make_float2(kc, kc);
    }
    __syncthreads();

    // ------------------------------------------------------------------
    // 4 points per thread (2 packed pairs)
    // ------------------------------------------------------------------
    int base = tile * PTS_PER_BLOCK;
    int pA = base + threadIdx.x;
    int pB = pA + BLOCK_THREADS;
    int pC = pB + BLOCK_THREADS;
    int pD = pC + BLOCK_THREADS;
    bool vA = pA < P, vB = pB < P, vC = pC < P, vD = pD < P;
    int lA = vA ? pA : 0, lB = vB ? pB : 0, lC = vC ? pC : 0, lD = vD ? pD : 0;

    float pxA = pts[3 * lA + 0], pyA = pts[3 * lA + 1], pzA = pts[3 * lA + 2];
    float pxB = pts[3 * lB + 0], pyB = pts[3 * lB + 1], pzB = pts[3 * lB + 2];
    float pxC = pts[3 * lC + 0], pyC = pts[3 * lC + 1], pzC = pts[3 * lC + 2];
    float pxD = pts[3 * lD + 0], pyD = pts[3 * lD + 1], pzD = pts[3 * lD + 2];

    unsigned long long px1 = pk2(pxA, pxB), py1 = pk2(pyA, pyB), pz1 = pk2(pzA, pzB);
    unsigned long long px2 = pk2(pxC, pxD), py2 = pk2(pyC, pyD), pz2 = pk2(pzC, pzD);

    float q2A = SS2 * (pxA * pxA + pyA * pyA + pzA * pzA);
    float q2B = SS2 * (pxB * pxB + pyB * pyB + pzB * pzB);
    float q2C = SS2 * (pxC * pxC + pyC * pyC + pzC * pzC);
    float q2D = SS2 * (pxD * pxD + pyD * pyD + pzD * pzD);

    unsigned long long ax1 = 0ull, ay1 = 0ull, az1 = 0ull, S1 = 0ull;
    unsigned long long ax2 = 0ull, ay2 = 0ull, az2 = 0ull, S2 = 0ull;

    const ulonglong2* sm = (const ulonglong2*)sf;

#pragma unroll 2
    for (int n = 0; n < nNodes; ++n) {
        ulonglong2 a0 = sm[8 * n + 0];
        ulonglong2 a1 = sm[8 * n + 1];
        ulonglong2 a2 = sm[8 * n + 2];
        ulonglong2 a3 = sm[8 * n + 3];
        ulonglong2 a4 = sm[8 * n + 4];
        ulonglong2 a5 = sm[8 * n + 5];
        ulonglong2 a6 = sm[8 * n + 6];  // (kx, ky)
        ulonglong2 a7 = sm[8 * n + 7];  // (kz, kc)

        {
            unsigned long long dot = fma2(a6.x, px1, fma2(a6.y, py1, fma2(a7.x, pz1, a7.y)));
            float d0, d1;
            upk2(dot, d0, d1);
            float w0 = ex2f(d0 - q2A);
            float w1 = ex2f(d1 - q2B);
            unsigned long long ww = pk2(w0, w1);

            unsigned long long y0 = fma2(a0.x, px1, fma2(a0.y, py1, fma2(a1.x, pz1, a1.y)));
            unsigned long long y1 = fma2(a2.x, px1, fma2(a2.y, py1, fma2(a3.x, pz1, a3.y)));
            unsigned long long y2 = fma2(a4.x, px1, fma2(a4.y, py1, fma2(a5.x, pz1, a5.y)));

            ax1 = fma2(ww, y0, ax1);
            ay1 = fma2(ww, y1, ay1);
            az1 = fma2(ww, y2, az1);
            S1 = add2(S1, ww);
        }
        {
            unsigned long long dot = fma2(a6.x, px2, fma2(a6.y, py2, fma2(a7.x, pz2, a7.y)));
            float d0, d1;
            upk2(dot, d0, d1);
            float w0 = ex2f(d0 - q2C);
            float w1 = ex2f(d1 - q2D);
            unsigned long long ww = pk2(w0, w1);

            unsigned long long y0 = fma2(a0.x, px2, fma2(a0.y, py2, fma2(a1.x, pz2, a1.y)));
            unsigned long long y1 = fma2(a2.x, px2, fma2(a2.y, py2, fma2(a3.x, pz2, a3.y)));
            unsigned long long y2 = fma2(a4.x, px2, fma2(a4.y, py2, fma2(a5.x, pz2, a5.y)));

            ax2 = fma2(ww, y0, ax2);
            ay2 = fma2(ww, y1, ay2);
            az2 = fma2(ww, y2, az2);
            S2 = add2(S2, ww);
        }
    }

    float axA, axB, ayA, ayB, azA, azB, SA, SB;
    upk2(ax1, axA, axB);
    upk2(ay1, ayA, ayB);
    upk2(az1, azA, azB);
    upk2(S1, SA, SB);
    float axC, axD, ayC, ayD, azC, azD, SC, SD;
    upk2(ax2, axC, axD);
    upk2(ay2, ayC, ayD);
    upk2(az2, azC, azD);
    upk2(S2, SC, SD);

    float4* gp = g_part + (size_t)split * P;
    if (vA) gp[pA] = make_float4(axA, ayA, azA, SA);
    if (vB) gp[pB] = make_float4(axB, ayB, azB, SB);
    if (vC) gp[pC] = make_float4(axC, ayC, azC, SC);
    if (vD) gp[pD] = make_float4(axD, ayD, azD, SD);

    // ------------------------------------------------------------------
    // Last split-block of this tile combines (fixed split order -> deterministic)
    // ------------------------------------------------------------------
    __threadfence();
    __shared__ unsigned int sOld;
    if (threadIdx.x == 0)
        sOld = atomicAdd(&g_tilecount[tile], 1u);
    __syncthreads();
    if ((sOld % NSPLIT) != (NSPLIT - 1)) return;

#pragma unroll
    for (int q = 0; q < 4; ++q) {
        int p = base + q * BLOCK_THREADS + threadIdx.x;
        if (p >= P) break;
        float ax = 0.0f, ay = 0.0f, az = 0.0f, S = 0.0f;
#pragma unroll
        for (int s = 0; s < NSPLIT; ++s) {
            float4 v = __ldcg(&g_part[(size_t)s * P + p]);  // L2-coherent read
            ax += v.x; ay += v.y; az += v.z; S += v.w;
        }
        float inv = 1.0f / (S + 1e-5f);
        out[3 * p + 0] = ax * inv;
        out[3 * p + 1] = ay * inv;
        out[3 * p + 2] = az * inv;
    }
}

// ---------------------------------------------------------------------------
extern "C" void kernel_launch(void* const* d_in, const int* in_sizes, int n_in,
                              void* d_out, int out_size) {
    const float* points  = (const float*)d_in[0];
    const float* cp      = (const float*)d_in[1];
    const float* rot_vec = (const float*)d_in[2];
    const float* t       = (const float*)d_in[3];
    const int*   edges   = (const int*)d_in[4];

    float* out = (float*)d_out;

    int P = in_sizes[0] / 3;
    if (P > MAXP) P = MAXP;  // defensive (scratch bound)
    int N = in_sizes[1] / 3;
    int E = in_sizes[4] / 2;

    int nTiles = (P + PTS_PER_BLOCK - 1) / PTS_PER_BLOCK;
    int chunk = (N + NSPLIT - 1) / NSPLIT;
    size_t smem = (size_t)chunk * 16 * sizeof(float2);  // 128 B per node

    main_kernel<<<nTiles * NSPLIT + 1, BLOCK_THREADS, smem>>>(
        points, cp, rot_vec, t, edges, out, N, P, E, nTiles, chunk);
}